// round 1
// baseline (speedup 1.0000x reference)
#include <cuda_runtime.h>

#define BB 4
#define SS 2048
#define HH 1024
#define NHH 16
#define DD 64
#define M_TOT (BB*SS)   // 8192

// Scratch (allocation-free rule: __device__ globals)
__device__ float g_Q[BB*NHH*SS*DD];
__device__ float g_K[BB*NHH*SS*DD];
__device__ float g_V[BB*NHH*SS*DD];
__device__ float g_O[BB*SS*HH];

typedef unsigned long long u64;

__device__ __forceinline__ u64 pk2(float lo, float hi){
    u64 r; asm("mov.b64 %0, {%1, %2};" : "=l"(r) : "f"(lo), "f"(hi)); return r;
}
__device__ __forceinline__ void upk2(float &lo, float &hi, u64 v){
    asm("mov.b64 {%0, %1}, %2;" : "=f"(lo), "=f"(hi) : "l"(v));
}
__device__ __forceinline__ void fma2(u64 &d, u64 a, u64 b){
    asm("fma.rn.f32x2 %0, %1, %2, %0;" : "+l"(d) : "l"(a), "l"(b));
}
__device__ __forceinline__ void mul2(u64 &d, u64 a){
    asm("mul.rn.f32x2 %0, %0, %1;" : "+l"(d) : "l"(a));
}

// ---------------------------------------------------------------------------
// SGEMM: out[M=8192, N=1024] = A[M,1024] @ W[N,1024]^T + bias
// MODE 0: scatter to [B, NH, S, D]   MODE 1: row-major [M, N]
// ---------------------------------------------------------------------------
template<int MODE>
__global__ void __launch_bounds__(256) sgemm_kernel(
    const float* __restrict__ A, const float* __restrict__ W,
    const float* __restrict__ bias, float* __restrict__ out)
{
    __shared__ float As[8][128];
    __shared__ float Bs[8][128];
    const int tid = threadIdx.x;
    const int m0 = blockIdx.y * 128;
    const int n0 = blockIdx.x * 128;
    const int lr = tid >> 1;           // 0..127
    const int lc = (tid & 1) * 4;      // 0 or 4
    const float* Ap = A + (m0 + lr) * 1024 + lc;
    const float* Wp = W + (n0 + lr) * 1024 + lc;
    const int tx = tid & 15;
    const int ty = tid >> 4;

    u64 acc[8][4];
    #pragma unroll
    for (int i = 0; i < 8; i++)
        #pragma unroll
        for (int j = 0; j < 4; j++) acc[i][j] = 0ull;  // packed (0.0f, 0.0f)

    for (int k0 = 0; k0 < 1024; k0 += 8) {
        float4 a4 = *(const float4*)(Ap + k0);
        float4 b4 = *(const float4*)(Wp + k0);
        __syncthreads();
        As[lc+0][lr] = a4.x; As[lc+1][lr] = a4.y; As[lc+2][lr] = a4.z; As[lc+3][lr] = a4.w;
        Bs[lc+0][lr] = b4.x; Bs[lc+1][lr] = b4.y; Bs[lc+2][lr] = b4.z; Bs[lc+3][lr] = b4.w;
        __syncthreads();
        #pragma unroll
        for (int k = 0; k < 8; k++) {
            float4 aa0 = *(const float4*)&As[k][ty*8];
            float4 aa1 = *(const float4*)&As[k][ty*8+4];
            float4 bb0 = *(const float4*)&Bs[k][tx*8];
            float4 bb1 = *(const float4*)&Bs[k][tx*8+4];
            u64 bp[4];
            bp[0] = pk2(bb0.x, bb0.y); bp[1] = pk2(bb0.z, bb0.w);
            bp[2] = pk2(bb1.x, bb1.y); bp[3] = pk2(bb1.z, bb1.w);
            float av[8] = {aa0.x,aa0.y,aa0.z,aa0.w,aa1.x,aa1.y,aa1.z,aa1.w};
            #pragma unroll
            for (int i = 0; i < 8; i++) {
                u64 ap = pk2(av[i], av[i]);
                #pragma unroll
                for (int j = 0; j < 4; j++) fma2(acc[i][j], ap, bp[j]);
            }
        }
    }

    #pragma unroll
    for (int i = 0; i < 8; i++) {
        int r = m0 + ty*8 + i;
        #pragma unroll
        for (int j = 0; j < 4; j++) {
            float lo, hi; upk2(lo, hi, acc[i][j]);
            int c0 = n0 + tx*8 + 2*j;
            float v0 = lo + bias[c0];
            float v1 = hi + bias[c0+1];
            if (MODE == 0) {
                int b  = r >> 11;          // r / S
                int s  = r & (SS - 1);
                int h0 = c0 >> 6;          // c0 / D
                int d0 = c0 & 63;          // pair never crosses head (c0 even)
                float* o = out + (((b*NHH + h0)*SS + s)*DD + d0);
                o[0] = v0; o[1] = v1;
            } else {
                out[r*1024 + c0]     = v0;
                out[r*1024 + c0 + 1] = v1;
            }
        }
    }
}

// ---------------------------------------------------------------------------
// Flash attention (non-causal), fp32, online softmax.
// Grid: (S/64, NH, B); block 256.  64-row Q tile, KV tiles of 64.
// Smem: Qs/Ks d-major [64][68] (q pre-scaled by 1/sqrt(D)); Vs row-major
// [64][68]; Ps [64][68].
// ---------------------------------------------------------------------------
#define PAD 68
#define TILE_F (64*PAD)

__global__ void __launch_bounds__(256) attn_kernel(
    const float* __restrict__ Q, const float* __restrict__ K,
    const float* __restrict__ V, float* __restrict__ O)
{
    extern __shared__ float smf[];
    float* Qs = smf;               // [d][row]
    float* Ks = smf + TILE_F;      // [d][col]
    float* Vs = smf + 2*TILE_F;    // [row][d]
    float* Ps = smf + 3*TILE_F;    // [qrow][kcol]

    const int tid = threadIdx.x;
    const int tx  = tid & 15;
    const int ty  = tid >> 4;
    const int q0  = blockIdx.x * 64;
    const int h   = blockIdx.y;
    const int b   = blockIdx.z;
    const int base = ((b*NHH + h)*SS) * DD;

    const int lr = tid >> 2;          // 0..63 (row)
    const int lcb = (tid & 3) * 16;   // col base

    // Load Q tile transposed, pre-scaled by 1/sqrt(64) = 0.125
    {
        const float* qp = Q + base + (q0 + lr)*DD + lcb;
        #pragma unroll
        for (int j = 0; j < 4; j++) {
            float4 v = *(const float4*)(qp + 4*j);
            int d0 = lcb + 4*j;
            Qs[(d0+0)*PAD + lr] = v.x * 0.125f;
            Qs[(d0+1)*PAD + lr] = v.y * 0.125f;
            Qs[(d0+2)*PAD + lr] = v.z * 0.125f;
            Qs[(d0+3)*PAD + lr] = v.w * 0.125f;
        }
    }

    u64 oacc[4][2] = {{0ull,0ull},{0ull,0ull},{0ull,0ull},{0ull,0ull}};
    float mrow[4] = {-3.402823466e38f, -3.402823466e38f, -3.402823466e38f, -3.402823466e38f};
    float lsum[4] = {0.f, 0.f, 0.f, 0.f};

    for (int k0 = 0; k0 < SS; k0 += 64) {
        __syncthreads();   // prev-iter PV done (and Q stores visible on iter 0)
        {
            const float* kp = K + base + (k0 + lr)*DD + lcb;
            const float* vp = V + base + (k0 + lr)*DD + lcb;
            #pragma unroll
            for (int j = 0; j < 4; j++) {
                int d0 = lcb + 4*j;
                float4 kv = *(const float4*)(kp + 4*j);
                Ks[(d0+0)*PAD + lr] = kv.x;
                Ks[(d0+1)*PAD + lr] = kv.y;
                Ks[(d0+2)*PAD + lr] = kv.z;
                Ks[(d0+3)*PAD + lr] = kv.w;
                float4 vv = *(const float4*)(vp + 4*j);
                *(float4*)&Vs[lr*PAD + d0] = vv;
            }
        }
        __syncthreads();

        // Scores: sc[i][j] = sum_d Qs[d][ty*4+i] * Ks[d][tx*4+j]
        u64 sc[4][2] = {{0ull,0ull},{0ull,0ull},{0ull,0ull},{0ull,0ull}};
        #pragma unroll 16
        for (int d = 0; d < 64; d++) {
            float4 q4 = *(const float4*)&Qs[d*PAD + ty*4];
            float4 k4 = *(const float4*)&Ks[d*PAD + tx*4];
            u64 kp0 = pk2(k4.x, k4.y), kp1 = pk2(k4.z, k4.w);
            float qa[4] = {q4.x, q4.y, q4.z, q4.w};
            #pragma unroll
            for (int i = 0; i < 4; i++) {
                u64 qd = pk2(qa[i], qa[i]);
                fma2(sc[i][0], qd, kp0);
                fma2(sc[i][1], qd, kp1);
            }
        }

        // Online softmax update per q-row (16 tx threads share a row-group)
        #pragma unroll
        for (int i = 0; i < 4; i++) {
            float s0, s1, s2, s3;
            upk2(s0, s1, sc[i][0]);
            upk2(s2, s3, sc[i][1]);
            float mx = fmaxf(fmaxf(s0, s1), fmaxf(s2, s3));
            #pragma unroll
            for (int off = 1; off < 16; off <<= 1)
                mx = fmaxf(mx, __shfl_xor_sync(0xffffffffu, mx, off));
            float mnew = fmaxf(mrow[i], mx);
            float alpha = __expf(mrow[i] - mnew);
            mrow[i] = mnew;
            float p0 = __expf(s0 - mnew);
            float p1 = __expf(s1 - mnew);
            float p2 = __expf(s2 - mnew);
            float p3 = __expf(s3 - mnew);
            float ps = p0 + p1 + p2 + p3;
            #pragma unroll
            for (int off = 1; off < 16; off <<= 1)
                ps += __shfl_xor_sync(0xffffffffu, ps, off);
            lsum[i] = lsum[i] * alpha + ps;
            u64 al2 = pk2(alpha, alpha);
            mul2(oacc[i][0], al2);
            mul2(oacc[i][1], al2);
            *(float4*)&Ps[(ty*4 + i)*PAD + tx*4] = make_float4(p0, p1, p2, p3);
        }
        __syncthreads();

        // PV: oacc[i][dc] += Ps[qrow][j] * Vs[j][dc]
        #pragma unroll 8
        for (int j = 0; j < 64; j++) {
            float4 v4 = *(const float4*)&Vs[j*PAD + tx*4];
            u64 vp0 = pk2(v4.x, v4.y), vp1 = pk2(v4.z, v4.w);
            #pragma unroll
            for (int i = 0; i < 4; i++) {
                float pv = Ps[(ty*4 + i)*PAD + j];
                u64 pd = pk2(pv, pv);
                fma2(oacc[i][0], pd, vp0);
                fma2(oacc[i][1], pd, vp1);
            }
        }
    }

    // Epilogue: write [B, S, H] row-major (feeds the final GEMM coalesced)
    #pragma unroll
    for (int i = 0; i < 4; i++) {
        float inv = 1.0f / lsum[i];
        float o0, o1, o2, o3;
        upk2(o0, o1, oacc[i][0]);
        upk2(o2, o3, oacc[i][1]);
        int row = q0 + ty*4 + i;
        float* op = O + (b*SS + row)*HH + h*DD + tx*4;
        op[0] = o0*inv; op[1] = o1*inv; op[2] = o2*inv; op[3] = o3*inv;
    }
}

// ---------------------------------------------------------------------------
extern "C" void kernel_launch(void* const* d_in, const int* in_sizes, int n_in,
                              void* d_out, int out_size)
{
    const float* x  = (const float*)d_in[0];
    const float* Wq = (const float*)d_in[1];
    const float* bq = (const float*)d_in[2];
    const float* Wk = (const float*)d_in[3];
    const float* bk = (const float*)d_in[4];
    const float* Wv = (const float*)d_in[5];
    const float* bv = (const float*)d_in[6];
    const float* Wo = (const float*)d_in[7];
    const float* bo = (const float*)d_in[8];
    float* out = (float*)d_out;

    void *pq, *pk, *pv, *po;
    cudaGetSymbolAddress(&pq, g_Q);
    cudaGetSymbolAddress(&pk, g_K);
    cudaGetSymbolAddress(&pv, g_V);
    cudaGetSymbolAddress(&po, g_O);

    dim3 gg(1024/128, M_TOT/128);   // (8, 64)
    sgemm_kernel<0><<<gg, 256>>>(x, Wq, bq, (float*)pq);
    sgemm_kernel<0><<<gg, 256>>>(x, Wk, bk, (float*)pk);
    sgemm_kernel<0><<<gg, 256>>>(x, Wv, bv, (float*)pv);

    const int smem = 4 * TILE_F * (int)sizeof(float);  // 69632 B
    cudaFuncSetAttribute(attn_kernel, cudaFuncAttributeMaxDynamicSharedMemorySize, smem);
    attn_kernel<<<dim3(SS/64, NHH, BB), 256, smem>>>(
        (const float*)pq, (const float*)pk, (const float*)pv, (float*)po);

    sgemm_kernel<1><<<gg, 256>>>((const float*)po, Wo, bo, out);
}

// round 2
// speedup vs baseline: 1.0549x; 1.0549x over previous
#include <cuda_runtime.h>

#define BB 4
#define SS 2048
#define HH 1024
#define NHH 16
#define DD 64
#define M_TOT (BB*SS)   // 8192

// Scratch (allocation-free rule: __device__ globals)
__device__ float g_Q[BB*NHH*SS*DD];
__device__ float g_K[BB*NHH*SS*DD];
__device__ float g_V[BB*NHH*SS*DD];
__device__ float g_O[BB*SS*HH];

typedef unsigned long long u64;

__device__ __forceinline__ u64 pk2(float lo, float hi){
    u64 r; asm("mov.b64 %0, {%1, %2};" : "=l"(r) : "f"(lo), "f"(hi)); return r;
}
__device__ __forceinline__ void upk2(float &lo, float &hi, u64 v){
    asm("mov.b64 {%0, %1}, %2;" : "=f"(lo), "=f"(hi) : "l"(v));
}
__device__ __forceinline__ void fma2(u64 &d, u64 a, u64 b){
    asm("fma.rn.f32x2 %0, %1, %2, %0;" : "+l"(d) : "l"(a), "l"(b));
}
__device__ __forceinline__ void mul2(u64 &d, u64 a){
    asm("mul.rn.f32x2 %0, %0, %1;" : "+l"(d) : "l"(a));
}

// ---------------------------------------------------------------------------
// SGEMM: out[M=8192, N=1024] = A[M,1024] @ W[N,1024]^T + bias
// MODE 0: scatter to [B, NH, S, D]   MODE 1: row-major [M, N]
// ---------------------------------------------------------------------------
template<int MODE>
__global__ void __launch_bounds__(256) sgemm_kernel(
    const float* __restrict__ A, const float* __restrict__ W,
    const float* __restrict__ bias, float* __restrict__ out)
{
    __shared__ float As[8][128];
    __shared__ float Bs[8][128];
    const int tid = threadIdx.x;
    const int m0 = blockIdx.y * 128;
    const int n0 = blockIdx.x * 128;
    const int lr = tid >> 1;           // 0..127
    const int lc = (tid & 1) * 4;      // 0 or 4
    const float* Ap = A + (m0 + lr) * 1024 + lc;
    const float* Wp = W + (n0 + lr) * 1024 + lc;
    const int tx = tid & 15;
    const int ty = tid >> 4;

    u64 acc[8][4];
    #pragma unroll
    for (int i = 0; i < 8; i++)
        #pragma unroll
        for (int j = 0; j < 4; j++) acc[i][j] = 0ull;  // packed (0.0f, 0.0f)

    for (int k0 = 0; k0 < 1024; k0 += 8) {
        float4 a4 = *(const float4*)(Ap + k0);
        float4 b4 = *(const float4*)(Wp + k0);
        __syncthreads();
        As[lc+0][lr] = a4.x; As[lc+1][lr] = a4.y; As[lc+2][lr] = a4.z; As[lc+3][lr] = a4.w;
        Bs[lc+0][lr] = b4.x; Bs[lc+1][lr] = b4.y; Bs[lc+2][lr] = b4.z; Bs[lc+3][lr] = b4.w;
        __syncthreads();
        #pragma unroll
        for (int k = 0; k < 8; k++) {
            float4 aa0 = *(const float4*)&As[k][ty*8];
            float4 aa1 = *(const float4*)&As[k][ty*8+4];
            float4 bb0 = *(const float4*)&Bs[k][tx*8];
            float4 bb1 = *(const float4*)&Bs[k][tx*8+4];
            u64 bp[4];
            bp[0] = pk2(bb0.x, bb0.y); bp[1] = pk2(bb0.z, bb0.w);
            bp[2] = pk2(bb1.x, bb1.y); bp[3] = pk2(bb1.z, bb1.w);
            float av[8] = {aa0.x,aa0.y,aa0.z,aa0.w,aa1.x,aa1.y,aa1.z,aa1.w};
            #pragma unroll
            for (int i = 0; i < 8; i++) {
                u64 ap = pk2(av[i], av[i]);
                #pragma unroll
                for (int j = 0; j < 4; j++) fma2(acc[i][j], ap, bp[j]);
            }
        }
    }

    #pragma unroll
    for (int i = 0; i < 8; i++) {
        int r = m0 + ty*8 + i;
        #pragma unroll
        for (int j = 0; j < 4; j++) {
            float lo, hi; upk2(lo, hi, acc[i][j]);
            int c0 = n0 + tx*8 + 2*j;
            float v0 = lo + bias[c0];
            float v1 = hi + bias[c0+1];
            if (MODE == 0) {
                int b  = r >> 11;          // r / S
                int s  = r & (SS - 1);
                int h0 = c0 >> 6;          // c0 / D
                int d0 = c0 & 63;          // pair never crosses head (c0 even)
                float* o = out + (((b*NHH + h0)*SS + s)*DD + d0);
                o[0] = v0; o[1] = v1;
            } else {
                out[r*1024 + c0]     = v0;
                out[r*1024 + c0 + 1] = v1;
            }
        }
    }
}

// ---------------------------------------------------------------------------
// Flash attention (non-causal), fp32, online softmax.
// Grid: (S/64, NH, B); block 256.  64-row Q tile, KV tiles of 64.
// Smem: Qs/Ks d-major [64][68] (q pre-scaled by 1/sqrt(D)); Vs row-major
// [64][68]; Ps [64][68].
// ---------------------------------------------------------------------------
#define PAD 68
#define TILE_F (64*PAD)

__global__ void __launch_bounds__(256) attn_kernel(
    const float* __restrict__ Q, const float* __restrict__ K,
    const float* __restrict__ V, float* __restrict__ O)
{
    extern __shared__ float smf[];
    float* Qs = smf;               // [d][row]
    float* Ks = smf + TILE_F;      // [d][col]
    float* Vs = smf + 2*TILE_F;    // [row][d]
    float* Ps = smf + 3*TILE_F;    // [qrow][kcol]

    const int tid = threadIdx.x;
    const int tx  = tid & 15;
    const int ty  = tid >> 4;
    const int q0  = blockIdx.x * 64;
    const int h   = blockIdx.y;
    const int b   = blockIdx.z;
    const int base = ((b*NHH + h)*SS) * DD;

    const int lr = tid >> 2;          // 0..63 (row)
    const int lcb = (tid & 3) * 16;   // col base

    // Load Q tile transposed, pre-scaled by 1/sqrt(64) = 0.125
    {
        const float* qp = Q + base + (q0 + lr)*DD + lcb;
        #pragma unroll
        for (int j = 0; j < 4; j++) {
            float4 v = *(const float4*)(qp + 4*j);
            int d0 = lcb + 4*j;
            Qs[(d0+0)*PAD + lr] = v.x * 0.125f;
            Qs[(d0+1)*PAD + lr] = v.y * 0.125f;
            Qs[(d0+2)*PAD + lr] = v.z * 0.125f;
            Qs[(d0+3)*PAD + lr] = v.w * 0.125f;
        }
    }

    u64 oacc[4][2] = {{0ull,0ull},{0ull,0ull},{0ull,0ull},{0ull,0ull}};
    float mrow[4] = {-3.402823466e38f, -3.402823466e38f, -3.402823466e38f, -3.402823466e38f};
    float lsum[4] = {0.f, 0.f, 0.f, 0.f};

    for (int k0 = 0; k0 < SS; k0 += 64) {
        __syncthreads();   // prev-iter PV done (and Q stores visible on iter 0)
        {
            const float* kp = K + base + (k0 + lr)*DD + lcb;
            const float* vp = V + base + (k0 + lr)*DD + lcb;
            #pragma unroll
            for (int j = 0; j < 4; j++) {
                int d0 = lcb + 4*j;
                float4 kv = *(const float4*)(kp + 4*j);
                Ks[(d0+0)*PAD + lr] = kv.x;
                Ks[(d0+1)*PAD + lr] = kv.y;
                Ks[(d0+2)*PAD + lr] = kv.z;
                Ks[(d0+3)*PAD + lr] = kv.w;
                float4 vv = *(const float4*)(vp + 4*j);
                *(float4*)&Vs[lr*PAD + d0] = vv;
            }
        }
        __syncthreads();

        // Scores: sc[i][j] = sum_d Qs[d][ty*4+i] * Ks[d][tx*4+j]
        u64 sc[4][2] = {{0ull,0ull},{0ull,0ull},{0ull,0ull},{0ull,0ull}};
        #pragma unroll 16
        for (int d = 0; d < 64; d++) {
            float4 q4 = *(const float4*)&Qs[d*PAD + ty*4];
            float4 k4 = *(const float4*)&Ks[d*PAD + tx*4];
            u64 kp0 = pk2(k4.x, k4.y), kp1 = pk2(k4.z, k4.w);
            float qa[4] = {q4.x, q4.y, q4.z, q4.w};
            #pragma unroll
            for (int i = 0; i < 4; i++) {
                u64 qd = pk2(qa[i], qa[i]);
                fma2(sc[i][0], qd, kp0);
                fma2(sc[i][1], qd, kp1);
            }
        }

        // Online softmax update per q-row (16 tx threads share a row-group)
        #pragma unroll
        for (int i = 0; i < 4; i++) {
            float s0, s1, s2, s3;
            upk2(s0, s1, sc[i][0]);
            upk2(s2, s3, sc[i][1]);
            float mx = fmaxf(fmaxf(s0, s1), fmaxf(s2, s3));
            #pragma unroll
            for (int off = 1; off < 16; off <<= 1)
                mx = fmaxf(mx, __shfl_xor_sync(0xffffffffu, mx, off));
            float mnew = fmaxf(mrow[i], mx);
            float alpha = __expf(mrow[i] - mnew);
            mrow[i] = mnew;
            float p0 = __expf(s0 - mnew);
            float p1 = __expf(s1 - mnew);
            float p2 = __expf(s2 - mnew);
            float p3 = __expf(s3 - mnew);
            float ps = p0 + p1 + p2 + p3;
            #pragma unroll
            for (int off = 1; off < 16; off <<= 1)
                ps += __shfl_xor_sync(0xffffffffu, ps, off);
            lsum[i] = lsum[i] * alpha + ps;
            u64 al2 = pk2(alpha, alpha);
            mul2(oacc[i][0], al2);
            mul2(oacc[i][1], al2);
            *(float4*)&Ps[(ty*4 + i)*PAD + tx*4] = make_float4(p0, p1, p2, p3);
        }
        __syncthreads();

        // PV: oacc[i][dc] += Ps[qrow][j] * Vs[j][dc]
        #pragma unroll 8
        for (int j = 0; j < 64; j++) {
            float4 v4 = *(const float4*)&Vs[j*PAD + tx*4];
            u64 vp0 = pk2(v4.x, v4.y), vp1 = pk2(v4.z, v4.w);
            #pragma unroll
            for (int i = 0; i < 4; i++) {
                float pv = Ps[(ty*4 + i)*PAD + j];
                u64 pd = pk2(pv, pv);
                fma2(oacc[i][0], pd, vp0);
                fma2(oacc[i][1], pd, vp1);
            }
        }
    }

    // Epilogue: write [B, S, H] row-major (feeds the final GEMM coalesced)
    #pragma unroll
    for (int i = 0; i < 4; i++) {
        float inv = 1.0f / lsum[i];
        float o0, o1, o2, o3;
        upk2(o0, o1, oacc[i][0]);
        upk2(o2, o3, oacc[i][1]);
        int row = q0 + ty*4 + i;
        float* op = O + (b*SS + row)*HH + h*DD + tx*4;
        op[0] = o0*inv; op[1] = o1*inv; op[2] = o2*inv; op[3] = o3*inv;
    }
}

// ---------------------------------------------------------------------------
extern "C" void kernel_launch(void* const* d_in, const int* in_sizes, int n_in,
                              void* d_out, int out_size)
{
    const float* x  = (const float*)d_in[0];
    const float* Wq = (const float*)d_in[1];
    const float* bq = (const float*)d_in[2];
    const float* Wk = (const float*)d_in[3];
    const float* bk = (const float*)d_in[4];
    const float* Wv = (const float*)d_in[5];
    const float* bv = (const float*)d_in[6];
    const float* Wo = (const float*)d_in[7];
    const float* bo = (const float*)d_in[8];
    float* out = (float*)d_out;

    void *pq, *pk, *pv, *po;
    cudaGetSymbolAddress(&pq, g_Q);
    cudaGetSymbolAddress(&pk, g_K);
    cudaGetSymbolAddress(&pv, g_V);
    cudaGetSymbolAddress(&po, g_O);

    dim3 gg(1024/128, M_TOT/128);   // (8, 64)
    sgemm_kernel<0><<<gg, 256>>>(x, Wq, bq, (float*)pq);
    sgemm_kernel<0><<<gg, 256>>>(x, Wk, bk, (float*)pk);
    sgemm_kernel<0><<<gg, 256>>>(x, Wv, bv, (float*)pv);

    const int smem = 4 * TILE_F * (int)sizeof(float);  // 69632 B
    cudaFuncSetAttribute(attn_kernel, cudaFuncAttributeMaxDynamicSharedMemorySize, smem);
    attn_kernel<<<dim3(SS/64, NHH, BB), 256, smem>>>(
        (const float*)pq, (const float*)pk, (const float*)pv, (float*)po);

    sgemm_kernel<1><<<gg, 256>>>((const float*)po, Wo, bo, out);
}